// round 17
// baseline (speedup 1.0000x reference)
#include <cuda_runtime.h>
#include <cuda_bf16.h>
#include <math.h>
#include <stdint.h>

#define B_ 64
#define T_ 512
#define H_ 1024
#define C_ 21

typedef unsigned long long ull;

// ---------------- f32x2 helpers ----------------
__device__ __forceinline__ ull pk2(float lo, float hi) {
    ull r; asm("mov.b64 %0, {%1, %2};" : "=l"(r) : "f"(lo), "f"(hi)); return r;
}
__device__ __forceinline__ void upk2(ull v, float& lo, float& hi) {
    asm("mov.b64 {%0, %1}, %2;" : "=f"(lo), "=f"(hi) : "l"(v));
}
__device__ __forceinline__ ull fma2(ull a, ull b, ull c) {
    ull d; asm("fma.rn.f32x2 %0, %1, %2, %3;" : "=l"(d) : "l"(a), "l"(b), "l"(c)); return d;
}
__device__ __forceinline__ ull mul2(ull a, ull b) {
    ull d; asm("mul.rn.f32x2 %0, %1, %2;" : "=l"(d) : "l"(a), "l"(b)); return d;
}
__device__ __forceinline__ ull add2(ull a, ull b) {
    ull d; asm("add.rn.f32x2 %0, %1, %2;" : "=l"(d) : "l"(a), "l"(b)); return d;
}

// ---------------- GEMM helpers (mma.sync, split-bf16) ----------------
#define KPAD 1032
#define SMEM_BYTES (2 * 24 * KPAD * 2)   // 99072 (GEMM role; CRF needs 43008)

__device__ __forceinline__ void mma_bf16(float* d,
                                         uint32_t a0, uint32_t a1,
                                         uint32_t a2, uint32_t a3,
                                         uint32_t b0, uint32_t b1) {
    asm volatile(
        "mma.sync.aligned.m16n8k16.row.col.f32.bf16.bf16.f32 "
        "{%0,%1,%2,%3}, {%4,%5,%6,%7}, {%8,%9}, {%0,%1,%2,%3};"
        : "+f"(d[0]), "+f"(d[1]), "+f"(d[2]), "+f"(d[3])
        : "r"(a0), "r"(a1), "r"(a2), "r"(a3), "r"(b0), "r"(b1));
}
__device__ __forceinline__ void split2(float2 f, uint32_t& hi, uint32_t& lo) {
    const uint32_t ux = __float_as_uint(f.x);
    const uint32_t uy = __float_as_uint(f.y);
    hi = __byte_perm(ux, uy, 0x7632);
    const float lx = f.x - __uint_as_float(ux & 0xffff0000u);
    const float ly = f.y - __uint_as_float(uy & 0xffff0000u);
    asm("cvt.rn.bf16x2.f32 %0, %1, %2;" : "=r"(lo) : "f"(ly), "f"(lx));
}

// ---------------- cross-block sync state (restored to 0 each run) ----------
__device__ int   g_cnt[4];     // tiles finished per t-chunk
__device__ int   g_done;       // finished CRF blocks
__device__ float g_llh[B_];

#define NBLK 320               // 64 CRF + 256 GEMM tiles

__global__ void __launch_bounds__(256, 2)
fused_kernel(const float* __restrict__ hs, const float* __restrict__ W,
             const float* __restrict__ bias, const float* __restrict__ trans,
             const float* __restrict__ startT, const float* __restrict__ endT,
             const int* __restrict__ att, const int* __restrict__ labels,
             float* __restrict__ out, float* __restrict__ loss)
{
    extern __shared__ char smem[];
    const int tid  = threadIdx.x;
    const int wid  = tid >> 5;
    const int lane = tid & 31;
    const unsigned FULL = 0xffffffffu;

    if (blockIdx.x >= B_) {
        // ======================= GEMM tile role =======================
        const int gidx = blockIdx.x - B_;
        const int tc   = gidx >> 6;       // t-chunk 0..3 (chunk-major order)
        const int bb   = gidx & 63;       // batch
        unsigned short* sBhi = (unsigned short*)smem;       // [24][KPAD]
        unsigned short* sBlo = sBhi + 24 * KPAD;

        const int g  = lane >> 2;
        const int tg = lane & 3;

        for (int i = tid; i < H_ * C_; i += 256) {
            const int k = i / C_;
            const int n = i - k * C_;
            const uint32_t u = __float_as_uint(W[i]);
            const float lo = __uint_as_float(u) - __uint_as_float(u & 0xffff0000u);
            sBhi[n * KPAD + k] = (unsigned short)(u >> 16);
            unsigned short ls;
            asm("{ .reg .b16 t; cvt.rn.bf16.f32 t, %1; mov.b16 %0, t; }"
                : "=h"(ls) : "f"(lo));
            sBlo[n * KPAD + k] = ls;
        }
        for (int i = tid; i < 3 * H_; i += 256) {
            const int n = 21 + (i >> 10);
            const int k = i & 1023;
            sBhi[n * KPAD + k] = 0;
            sBlo[n * KPAD + k] = 0;
        }
        __syncthreads();

        const int r0 = bb * T_ + tc * 128 + wid * 16 + g;
        const int r1 = r0 + 8;
        const float* pa0 = hs + (size_t)r0 * H_ + tg * 2;
        const float* pa1 = hs + (size_t)r1 * H_ + tg * 2;

        float acc[3][4];
#pragma unroll
        for (int no = 0; no < 3; no++)
#pragma unroll
            for (int p = 0; p < 4; p++) acc[no][p] = 0.f;

        float2 X0, X1, X2, X3, X4, X5, X6, X7;
        float2 Y0, Y1, Y2, Y3, Y4, Y5, Y6, Y7;

#define LOADPAIR(Bn, P) do {                                                \
        const int _k = (P) * 32;                                            \
        Bn##0 = *(const float2*)(pa0 + _k);                                 \
        Bn##1 = *(const float2*)(pa1 + _k);                                 \
        Bn##2 = *(const float2*)(pa0 + _k + 8);                             \
        Bn##3 = *(const float2*)(pa1 + _k + 8);                             \
        Bn##4 = *(const float2*)(pa0 + _k + 16);                            \
        Bn##5 = *(const float2*)(pa1 + _k + 16);                            \
        Bn##6 = *(const float2*)(pa0 + _k + 24);                            \
        Bn##7 = *(const float2*)(pa1 + _k + 24);                            \
    } while (0)

#define KSTEP(Fa, Fb, Fc, Fd, KS) do {                                      \
        uint32_t ah0, al0, ah1, al1, ah2, al2, ah3, al3;                    \
        split2(Fa, ah0, al0);                                               \
        split2(Fb, ah1, al1);                                               \
        split2(Fc, ah2, al2);                                               \
        split2(Fd, ah3, al3);                                               \
        const int _kb = (KS) * 16 + tg * 2;                                 \
        _Pragma("unroll")                                                   \
        for (int no = 0; no < 3; no++) {                                    \
            const int n = no * 8 + g;                                       \
            const unsigned short* ph = sBhi + n * KPAD + _kb;               \
            const unsigned short* pl = sBlo + n * KPAD + _kb;               \
            const uint32_t bh0 = *(const uint32_t*)(ph);                    \
            const uint32_t bh1 = *(const uint32_t*)(ph + 8);                \
            const uint32_t bl0 = *(const uint32_t*)(pl);                    \
            const uint32_t bl1 = *(const uint32_t*)(pl + 8);                \
            mma_bf16(acc[no], ah0, ah1, ah2, ah3, bh0, bh1);                \
            mma_bf16(acc[no], ah0, ah1, ah2, ah3, bl0, bl1);                \
            mma_bf16(acc[no], al0, al1, al2, al3, bh0, bh1);                \
        }                                                                   \
    } while (0)

        LOADPAIR(X, 0);
#pragma unroll 1
        for (int p = 0; p < 32; p += 2) {
            LOADPAIR(Y, p + 1);
            KSTEP(X0, X1, X2, X3, 2 * p);
            KSTEP(X4, X5, X6, X7, 2 * p + 1);
            if (p + 2 < 32) LOADPAIR(X, p + 2);
            KSTEP(Y0, Y1, Y2, Y3, 2 * p + 2);
            KSTEP(Y4, Y5, Y6, Y7, 2 * p + 3);
        }

        float* o0 = out + (size_t)r0 * C_;
        float* o1 = out + (size_t)r1 * C_;
#pragma unroll
        for (int no = 0; no < 3; no++) {
            const int c0 = no * 8 + tg * 2;
            const int c1 = c0 + 1;
            if (c0 < C_) {
                const float bz = bias[c0];
                o0[c0] = acc[no][0] + bz;
                o1[c0] = acc[no][2] + bz;
            }
            if (c1 < C_) {
                const float bz = bias[c1];
                o0[c1] = acc[no][1] + bz;
                o1[c1] = acc[no][3] + bz;
            }
        }
        __syncthreads();
        if (tid == 0) {
            __threadfence();
            atomicAdd(&g_cnt[tc], 1);   // release: tile's emissions visible
        }
        return;
    }

    // ======================= CRF role =======================
    const int b = blockIdx.x;
    float* sEexp = (float*)smem;                 // 43008 B of dynamic smem
    __shared__ float sNum;
    __shared__ int sL;

    const float* em = out + (size_t)b * T_ * C_;
    const int* tag = labels + b * T_;
    const int* mrow = att + b * T_;

    // sequence length (independent of GEMM)
    if (wid == 0) {
        int cnt = 0;
        for (int t = lane; t < T_; t += 32) {
            bool mk = (t == 0) ? true : (mrow[t] != 0 && tag[t] != -100);
            cnt += mk ? 1 : 0;
        }
#pragma unroll
        for (int o = 16; o; o >>= 1) cnt += __shfl_xor_sync(FULL, cnt, o);
        if (lane == 0) sL = cnt;
    }
    __syncthreads();
    const int L = sL;
    const int tcmax = (L - 1) >> 7;

    // recursion constants (independent of GEMM): warp 0 precomputes
    const int j = (lane < C_) ? lane : (C_ - 1);
    ull E2[11];
    float eend = 0.f;
    if (wid == 0) {
#pragma unroll
        for (int k = 0; k < 10; k++)
            E2[k] = pk2(__expf(trans[(2 * k) * C_ + j]),
                        __expf(trans[(2 * k + 1) * C_ + j]));
        E2[10] = pk2(__expf(trans[20 * C_ + j]), 0.f);
        eend = (lane < C_) ? __expf(endT[j]) : 0.f;
    }

    ull v2[11];
    float acc = 0.f;
    float logZ = 0.f;
    int t = 1;

#define CRF_STEP(TIDX, RENORM) do {                                          \
        const float eet = sEexp[(TIDX) * C_ + j];                            \
        ull ch0 = mul2(E2[0], v2[0]);                                        \
        ull ch1 = mul2(E2[1], v2[1]);                                        \
        ull ch2 = mul2(E2[2], v2[2]);                                        \
        ch0 = fma2(E2[3], v2[3], ch0);                                       \
        ch1 = fma2(E2[4], v2[4], ch1);                                       \
        ch2 = fma2(E2[5], v2[5], ch2);                                       \
        ch0 = fma2(E2[6], v2[6], ch0);                                       \
        ch1 = fma2(E2[7], v2[7], ch1);                                       \
        ch2 = fma2(E2[8], v2[8], ch2);                                       \
        ch0 = fma2(E2[9], v2[9], ch0);                                       \
        ch1 = fma2(E2[10], v2[10], ch1);                                     \
        ull s2 = add2(add2(ch0, ch1), ch2);                                  \
        float slo, shi; upk2(s2, slo, shi);                                  \
        float u = (slo + shi) * eet;                                         \
        if (RENORM) {                                                        \
            float cn = __shfl_sync(FULL, u, 0);                              \
            acc += __logf(cn);                                               \
            u *= __fdividef(1.f, cn);                                        \
        }                                                                    \
        _Pragma("unroll")                                                    \
        for (int k = 0; k < 10; k++)                                         \
            v2[k] = pk2(__shfl_sync(FULL, u, 2 * k),                         \
                        __shfl_sync(FULL, u, 2 * k + 1));                    \
        v2[10] = pk2(__shfl_sync(FULL, u, 20), 0.f);                         \
    } while (0)

    for (int tc = 0; tc <= tcmax; tc++) {
        // wait for all 64 tiles of this t-chunk (acquire)
        if (tid == 0) {
            while (atomicAdd(&g_cnt[tc], 0) < 64) __nanosleep(128);
        }
        __syncthreads();

        // stage exp(em) for this chunk (cold L1 -> reads hit fresh L2 data)
        const int t0 = tc * 128;
        const int t1 = (t0 + 128 < L) ? (t0 + 128) : L;
        for (int i = tid + t0 * C_; i < t1 * C_; i += 256)
            sEexp[i] = __expf(em[i]);
        __syncthreads();

        if (wid == 0) {
            if (tc == 0) {
                // init: w_j = exp(start_j)*exp(em0_j); normalize by w_0
                float w = __expf(startT[j]) * sEexp[j];
#pragma unroll
                for (int k = 0; k < 10; k++)
                    v2[k] = pk2(__shfl_sync(FULL, w, 2 * k),
                                __shfl_sync(FULL, w, 2 * k + 1));
                v2[10] = pk2(__shfl_sync(FULL, w, 20), 0.f);
                float w0 = __shfl_sync(FULL, w, 0);
                acc = __logf(w0);
                const float rw0 = __fdividef(1.f, w0);
                const ull rr = pk2(rw0, rw0);
#pragma unroll
                for (int k = 0; k < 11; k++) v2[k] = mul2(v2[k], rr);
            }
            while (t + 8 <= t1) {
                CRF_STEP(t + 0, 0);
                CRF_STEP(t + 1, 0);
                CRF_STEP(t + 2, 0);
                CRF_STEP(t + 3, 0);
                CRF_STEP(t + 4, 0);
                CRF_STEP(t + 5, 0);
                CRF_STEP(t + 6, 0);
                CRF_STEP(t + 7, 1);
                t += 8;
            }
            while (t < t1) { CRF_STEP(t, 1); t++; }
        }
        if (wid == 1 && tc == tcmax) {
            // numerator (all needed emissions now visible)
            float part = 0.f;
            for (int tt = 1 + lane; tt < L; tt += 32)
                part += trans[tag[tt - 1] * C_ + tag[tt]] + em[tt * C_ + tag[tt]];
#pragma unroll
            for (int o = 16; o; o >>= 1) part += __shfl_xor_sync(FULL, part, o);
            if (lane == 0)
                sNum = part + startT[tag[0]] + em[tag[0]] + endT[tag[L - 1]];
        }
    }

    if (wid == 0) {
        float vlo, vhi;
        upk2(v2[j >> 1], vlo, vhi);
        float vf = (j & 1) ? vhi : vlo;
        float z = vf * eend;
#pragma unroll
        for (int o = 16; o; o >>= 1) z += __shfl_xor_sync(FULL, z, o);
        logZ = acc + __logf(z);
    }
    __syncthreads();

    if (tid == 0) {
        g_llh[b] = sNum - logZ;
        __threadfence();
        const int my = atomicAdd(&g_done, 1);
        if (my == B_ - 1) {
            // last CRF block: wait for all GEMM tiles, reduce, reset state
#pragma unroll
            for (int c = 0; c < 4; c++)
                while (atomicAdd(&g_cnt[c], 0) < 64) __nanosleep(128);
            __threadfence();
            float s = 0.f;
            for (int i = 0; i < B_; i++) s += g_llh[i];
            loss[0] = -s / (float)B_;
            g_done = 0;
            g_cnt[0] = 0; g_cnt[1] = 0; g_cnt[2] = 0; g_cnt[3] = 0;
            __threadfence();
        }
    }
}

// ---------------- launch ----------------

extern "C" void kernel_launch(void* const* d_in, const int* in_sizes, int n_in,
                              void* d_out, int out_size)
{
    const float* hs     = (const float*)d_in[0];
    const float* W      = (const float*)d_in[1];
    const float* bias   = (const float*)d_in[2];
    const float* trans  = (const float*)d_in[3];
    const float* startT = (const float*)d_in[4];
    const float* endT   = (const float*)d_in[5];
    const int*   att    = (const int*)d_in[6];
    const int*   labels = (const int*)d_in[7];
    float* out  = (float*)d_out;
    float* loss = out + (out_size - 1);

    cudaFuncSetAttribute(fused_kernel, cudaFuncAttributeMaxDynamicSharedMemorySize,
                         SMEM_BYTES);

    fused_kernel<<<NBLK, 256, SMEM_BYTES>>>(hs, W, bias, trans, startT, endT,
                                            att, labels, out, loss);
}